// round 7
// baseline (speedup 1.0000x reference)
#include <cuda_runtime.h>
#include <cuda_bf16.h>
#include <cstdint>

#define BB 8
#define NN 1024
#define NP (BB*NN)
#define KK 20

// ---------------- scratch (device globals; no allocation allowed) -------------
__device__ float g_h1[NP*256];
__device__ float g_h2[NP*256];
__device__ float g_dist[(size_t)BB*NN*NN];
__device__ int   g_idx[NP*KK];
__device__ float g_xx[NP];
__device__ float4 g_wdp[8192];               // packed (W2 - W1), [c4][OUT]
__device__ uint32_t g_wh[256*64];            // W1 split hi, [o][c2] bf16x2
__device__ uint32_t g_wm[256*64];            // W1 split mid
__device__ uint32_t g_wl[256*64];            // W1 split lo
__device__ uint32_t g_hh[NP*64];             // h split hi, [p][c2] bf16x2
__device__ uint32_t g_hm[NP*64];             // h split mid
__device__ uint32_t g_hl[NP*64];             // h split lo
__device__ float g_base[(size_t)NP*256];     // (W2-W1)*ctr per (p,o)
__device__ float g_fused[(size_t)NP*512];
__device__ float g_psum[(size_t)NP*256];     // transposed: [o*P + p]
__device__ float g_pssq[(size_t)NP*256];
__device__ float g_scale[1024];
__device__ float g_shift[1024];
__device__ __nv_bfloat16 g_bh[1024*512];     // Wf split hi
__device__ __nv_bfloat16 g_bl[1024*512];     // Wf split lo

__device__ __forceinline__ void fma2(unsigned long long& d,
                                     unsigned long long a, unsigned long long b) {
    asm("fma.rn.f32x2 %0, %1, %2, %0;" : "+l"(d) : "l"(a), "l"(b));
}
__device__ __forceinline__ unsigned long long pack2(float lo, float hi) {
    unsigned long long r;
    asm("mov.b64 %0, {%1, %2};" : "=l"(r) : "f"(lo), "f"(hi));
    return r;
}
__device__ __forceinline__ void unpack2(float& lo, float& hi, unsigned long long v) {
    asm("mov.b64 {%0, %1}, %2;" : "=f"(lo), "=f"(hi) : "l"(v));
}
__device__ __forceinline__ uint32_t packbf2(float a, float b) {
    __nv_bfloat162 p;
    p.x = __float2bfloat16(a);
    p.y = __float2bfloat16(b);
    return *(uint32_t*)&p;
}
// 3-way bf16 split: v = h + m + l with |err| ~ 2^-26 |v|
__device__ __forceinline__ void split3(float v, float& h, float& m, float& l) {
    __nv_bfloat16 b0 = __float2bfloat16(v);
    h = __bfloat162float(b0);
    float r1 = v - h;
    __nv_bfloat16 b1 = __float2bfloat16(r1);
    m = __bfloat162float(b1);
    l = r1 - m;
}
// HMMA m16n8k16 bf16 -> fp32 accumulate
__device__ __forceinline__ void mma16816(float* c, const uint32_t* a, const uint32_t* b) {
    asm volatile("mma.sync.aligned.m16n8k16.row.col.f32.bf16.bf16.f32 "
        "{%0,%1,%2,%3}, {%4,%5,%6,%7}, {%8,%9}, {%0,%1,%2,%3};"
        : "+f"(c[0]), "+f"(c[1]), "+f"(c[2]), "+f"(c[3])
        : "r"(a[0]), "r"(a[1]), "r"(a[2]), "r"(a[3]), "r"(b[0]), "r"(b[1]));
}

// ---------------- ||x||^2 per point (input layer only) -------------------------
__global__ void xx_kernel(const float* __restrict__ h, int C) {
    int p = blockIdx.x;
    __shared__ float sh[64];
    float s = 0.f;
    for (int c = threadIdx.x; c < C; c += 64) {
        float v = h[(size_t)p*C + c];
        s += v*v;
    }
    sh[threadIdx.x] = s; __syncthreads();
    for (int st = 32; st > 0; st >>= 1) {
        if (threadIdx.x < st) sh[threadIdx.x] += sh[threadIdx.x + st];
        __syncthreads();
    }
    if (threadIdx.x == 0) g_xx[p] = sh[0];
}

// ---------------- neg_dist: 64x64 register-tiled GEMM + f32x2 ------------------
__global__ void __launch_bounds__(256) negdist_kernel(const float* __restrict__ h, int C) {
    __shared__ float As[16][68];
    __shared__ float Bs[16][68];
    int b  = blockIdx.z;
    int n0 = blockIdx.y * 64, m0 = blockIdx.x * 64;
    int tid = threadIdx.x;
    int tx = tid & 15, ty = tid >> 4;
    unsigned long long acc[4][2];
    #pragma unroll
    for (int i = 0; i < 4; i++) { acc[i][0] = 0ull; acc[i][1] = 0ull; }

    for (int c0 = 0; c0 < C; c0 += 16) {
        #pragma unroll
        for (int r = 0; r < 4; r++) {
            int idx = tid + r*256;
            int cc = idx & 15, n = idx >> 4;
            int c = c0 + cc;
            As[cc][n] = (c < C) ? h[((size_t)(b*NN) + n0 + n)*C + c] : 0.f;
            Bs[cc][n] = (c < C) ? h[((size_t)(b*NN) + m0 + n)*C + c] : 0.f;
        }
        __syncthreads();
        #pragma unroll
        for (int kk = 0; kk < 16; kk++) {
            float4 a = *(const float4*)&As[kk][ty*4];
            ulonglong2 bb = *(const ulonglong2*)&Bs[kk][tx*4];
            unsigned long long a0 = pack2(a.x, a.x);
            unsigned long long a1 = pack2(a.y, a.y);
            unsigned long long a2 = pack2(a.z, a.z);
            unsigned long long a3 = pack2(a.w, a.w);
            fma2(acc[0][0], a0, bb.x); fma2(acc[0][1], a0, bb.y);
            fma2(acc[1][0], a1, bb.x); fma2(acc[1][1], a1, bb.y);
            fma2(acc[2][0], a2, bb.x); fma2(acc[2][1], a2, bb.y);
            fma2(acc[3][0], a3, bb.x); fma2(acc[3][1], a3, bb.y);
        }
        __syncthreads();
    }
    #pragma unroll
    for (int i = 0; i < 4; i++) {
        int n = n0 + ty*4 + i;
        float xn = g_xx[b*NN + n];
        #pragma unroll
        for (int jp = 0; jp < 2; jp++) {
            float lo, hi;
            unpack2(lo, hi, acc[i][jp]);
            int m = m0 + tx*4 + jp*2;
            g_dist[((size_t)(b*NN) + n)*NN + m]     = 2.f*lo - xn - g_xx[b*NN + m];
            g_dist[((size_t)(b*NN) + n)*NN + m + 1] = 2.f*hi - xn - g_xx[b*NN + m + 1];
        }
    }
}

// ---------------- top-k: warp per point, register-resident --------------------
__global__ void topk_kernel() {
    int lane = threadIdx.x & 31;
    int p = blockIdx.x * 8 + (threadIdx.x >> 5);
    const float* row = g_dist + (size_t)p*NN;
    float v[32];
    #pragma unroll
    for (int j = 0; j < 32; j++) v[j] = row[j*32 + lane];
    float lm = -1e30f; int ls = 0;
    #pragma unroll
    for (int j = 0; j < 32; j++) {
        if (v[j] > lm) { lm = v[j]; ls = j; }
    }
    for (int k = 0; k < KK; k++) {
        float bv = lm; int gi = ls*32 + lane;
        #pragma unroll
        for (int off = 16; off > 0; off >>= 1) {
            float ov = __shfl_xor_sync(0xffffffffu, bv, off);
            int   og = __shfl_xor_sync(0xffffffffu, gi, off);
            if (ov > bv || (ov == bv && og < gi)) { bv = ov; gi = og; }
        }
        if (lane == 0) g_idx[p*KK + k] = gi;
        if (lane == (gi & 31)) {
            int bs = gi >> 5;
            float nm = -1e30f; int ns = 0;
            #pragma unroll
            for (int j = 0; j < 32; j++) {
                if (j == bs) v[j] = -1e30f;
                if (v[j] > nm) { nm = v[j]; ns = j; }
            }
            lm = nm; ls = ns;
        }
    }
}

// ---------------- Wd transform: W(out,2C) -> g_wdp[c4][OUT] -------------------
__global__ void wtrans_kernel(const float* __restrict__ W, int C, int Cp, int OUT) {
    int i = blockIdx.x*256 + threadIdx.x;
    int total = (Cp >> 2) * OUT;
    if (i >= total) return;
    int o = i % OUT;
    int c4 = i / OUT;
    float wd[4];
    #pragma unroll
    for (int j = 0; j < 4; j++) {
        int c = c4*4 + j;
        wd[j] = (c < C) ? (W[(size_t)o*2*C + C + c] - W[(size_t)o*2*C + c]) : 0.f;
    }
    g_wdp[i] = make_float4(wd[0], wd[1], wd[2], wd[3]);
}

// ---------------- W1 split: W(out,2C) -> g_wh/g_wm/g_wl [o][c2] ---------------
__global__ void wsplit_kernel(const float* __restrict__ W, int C, int C2, int OUT) {
    int i = blockIdx.x*256 + threadIdx.x;
    if (i >= OUT*C2) return;
    int o = i / C2, c2 = i - o*C2;
    float w0 = W[(size_t)o*2*C + 2*c2];
    float w1 = (2*c2 + 1 < C) ? W[(size_t)o*2*C + 2*c2 + 1] : 0.f;
    float h0, m0, l0, h1, m1, l1;
    split3(w0, h0, m0, l0);
    split3(w1, h1, m1, l1);
    g_wh[i] = packbf2(h0, h1);
    g_wm[i] = packbf2(m0, m1);
    g_wl[i] = packbf2(l0, l1);
}

// ---------------- x split: (B,N,3) -> g_hh/g_hm/g_hl stride 2 -----------------
__global__ void xsplit_kernel(const float* __restrict__ x) {
    int p = blockIdx.x*256 + threadIdx.x;
    if (p >= NP) return;
    float h0, m0, l0, h1, m1, l1, h2, m2, l2;
    split3(x[p*3],   h0, m0, l0);
    split3(x[p*3+1], h1, m1, l1);
    split3(x[p*3+2], h2, m2, l2);
    g_hh[p*2+0] = packbf2(h0, h1);
    g_hh[p*2+1] = packbf2(h2, 0.f);
    g_hm[p*2+0] = packbf2(m0, m1);
    g_hm[p*2+1] = packbf2(m2, 0.f);
    g_hl[p*2+0] = packbf2(l0, l1);
    g_hl[p*2+1] = packbf2(l2, 0.f);
}

// ---------------- base = (W2-W1)*ctr per (p,o) --------------------------------
__global__ void base_kernel(const float* __restrict__ h, int C, int Cp, int OUT) {
    extern __shared__ float ctr[];
    int p = blockIdx.x, o = threadIdx.x;
    for (int c = o; c < Cp; c += OUT)
        ctr[c] = (c < C) ? h[(size_t)p*C + c] : 0.f;
    __syncthreads();
    int C4 = Cp >> 2;
    const float4* c4p = (const float4*)ctr;
    float s = 0.f;
    for (int c4 = 0; c4 < C4; c4++) {
        float4 w = g_wdp[c4*OUT + o];
        float4 cv = c4p[c4];
        s += w.x*cv.x + w.y*cv.y + w.z*cv.z + w.w*cv.w;
    }
    g_base[(size_t)p*OUT + o] = s;
}

// ---------------- edge conv via HMMA multi-term bf16 split --------------------
// Block: 4 points (128 A rows = 4 x 32 padded k), NT = NI*32 output cols.
// 8 warps (2m x 4n), warp tile 64 x (NI*8).
// HP=true: 3-way split, 8 products (err ~1e-7, safe to feed KNN).
// HP=false: 2-way split, 3 products (err ~1e-5, last layer only).
template<int NI, bool HP>
__global__ void __launch_bounds__(256) edgemma_kernel(
    int C2, int OUT, int foff, int nks, int nchunks)
{
    const int NT = NI * 32;
    const int NA = HP ? 3 : 2;
    __shared__ uint32_t sA[NA][128*18];
    __shared__ uint32_t sB[NA][NT*18];
    __shared__ int nb[80];

    int tid = threadIdx.x, wid = tid >> 5, lane = tid & 31;
    int g = lane >> 2, t = lane & 3;
    int wm = wid >> 2, wn = wid & 3;
    int pbase = blockIdx.x * 4;
    int obase = blockIdx.y * NT;
    int batch_off = (pbase >> 10) << 10;

    if (tid < 80) nb[tid] = g_idx[(pbase + tid/20)*KK + (tid - (tid/20)*20)];

    float acc[4][NI][4];
    #pragma unroll
    for (int mi = 0; mi < 4; mi++)
        #pragma unroll
        for (int ni = 0; ni < NI; ni++)
            #pragma unroll
            for (int j = 0; j < 4; j++) acc[mi][ni][j] = 0.f;

    const uint32_t* hsrc[3] = {g_hh, g_hm, g_hl};
    const uint32_t* wsrc[3] = {g_wh, g_wm, g_wl};

    __syncthreads();

    for (int chunk = 0; chunk < nchunks; chunk++) {
        if (chunk > 0) __syncthreads();
        // A fill: 128 rows x 16 k-pairs (gathered neighbor features)
        for (int i = tid; i < 2048; i += 256) {
            int row = i >> 4, kp = i & 15;
            int k = row & 31, lp = row >> 5;
            int c2 = chunk*16 + kp;
            bool ok = (k < KK && c2 < C2);
            size_t idx = ok ? (size_t)(batch_off + nb[lp*20 + k])*C2 + c2 : 0;
            #pragma unroll
            for (int a = 0; a < NA; a++)
                sA[a][row*18 + kp] = ok ? hsrc[a][idx] : 0u;
        }
        // B fill: NT weight rows x 16 k-pairs
        for (int i = tid; i < NT*16; i += 256) {
            int row = i >> 4, kp = i & 15;
            int c2 = chunk*16 + kp;
            bool ok = (c2 < C2);
            size_t idx = ok ? (size_t)(obase + row)*C2 + c2 : 0;
            #pragma unroll
            for (int a = 0; a < NA; a++)
                sB[a][row*18 + kp] = ok ? wsrc[a][idx] : 0u;
        }
        __syncthreads();
        for (int ks = 0; ks < nks; ks++) {
            int kp0 = ks * 8;
            uint32_t af[NA][4][4];
            #pragma unroll
            for (int a = 0; a < NA; a++)
                #pragma unroll
                for (int mi = 0; mi < 4; mi++) {
                    int r = wm*64 + mi*16 + g;
                    af[a][mi][0] = sA[a][r*18 + kp0 + t];
                    af[a][mi][1] = sA[a][(r+8)*18 + kp0 + t];
                    af[a][mi][2] = sA[a][r*18 + kp0 + 4 + t];
                    af[a][mi][3] = sA[a][(r+8)*18 + kp0 + 4 + t];
                }
            uint32_t bf[NA][NI][2];
            #pragma unroll
            for (int a = 0; a < NA; a++)
                #pragma unroll
                for (int ni = 0; ni < NI; ni++) {
                    int n = wn*(NI*8) + ni*8 + g;
                    bf[a][ni][0] = sB[a][n*18 + kp0 + t];
                    bf[a][ni][1] = sB[a][n*18 + kp0 + 4 + t];
                }
            const int PL = HP ? 8 : 3;
            const int pa[8] = {0,0,1,0,2,1,1,2};
            const int pb[8] = {0,1,0,2,0,1,2,1};
            #pragma unroll
            for (int pr = 0; pr < PL; pr++)
                #pragma unroll
                for (int mi = 0; mi < 4; mi++)
                    #pragma unroll
                    for (int ni = 0; ni < NI; ni++)
                        mma16816(acc[mi][ni], af[pa[pr]][mi], bf[pb[pr]][ni]);
        }
    }

    // epilogue: per-point max / sum / sumsq over valid k rows
    #pragma unroll
    for (int half = 0; half < 2; half++) {
        int p = pbase + wm*2 + half;
        #pragma unroll
        for (int ni = 0; ni < NI; ni++) {
            #pragma unroll
            for (int j = 0; j < 2; j++) {
                float v0 = acc[half*2][ni][j];       // k = g
                float v1 = acc[half*2][ni][j+2];     // k = g+8
                float v2 = acc[half*2+1][ni][j];     // k = 16+g (valid g<4)
                bool ok2 = (g < 4);
                float mx = fmaxf(v0, v1);
                if (ok2) mx = fmaxf(mx, v2);
                float s = v0 + v1 + (ok2 ? v2 : 0.f);
                float q = v0*v0 + v1*v1 + (ok2 ? v2*v2 : 0.f);
                #pragma unroll
                for (int off = 4; off <= 16; off <<= 1) {
                    mx = fmaxf(mx, __shfl_xor_sync(0xffffffffu, mx, off));
                    s += __shfl_xor_sync(0xffffffffu, s, off);
                    q += __shfl_xor_sync(0xffffffffu, q, off);
                }
                if (g == 0) {
                    int o = obase + wn*(NI*8) + ni*8 + t*2 + j;
                    float b = g_base[(size_t)p*OUT + o];
                    g_fused[(size_t)p*512 + foff + o] = mx + b;
                    g_psum[(size_t)o*NP + p] = s + 20.f*b;
                    g_pssq[(size_t)o*NP + p] = q + 2.f*b*s + 20.f*b*b;
                }
            }
        }
    }
}

// ---------------- per-channel BN stats (coalesced, deterministic) -------------
__global__ void chanstats_kernel(const float* __restrict__ g,
                                 const float* __restrict__ bta,
                                 int P, float invM) {
    int o = blockIdx.x;
    __shared__ float ssum[256], ssq[256];
    const float* ps = g_psum + (size_t)o*P;
    const float* pq = g_pssq + (size_t)o*P;
    float s = 0.f, q = 0.f;
    for (int i = threadIdx.x; i < P; i += 256) { s += ps[i]; q += pq[i]; }
    ssum[threadIdx.x] = s; ssq[threadIdx.x] = q;
    __syncthreads();
    for (int st = 128; st > 0; st >>= 1) {
        if (threadIdx.x < st) {
            ssum[threadIdx.x] += ssum[threadIdx.x + st];
            ssq [threadIdx.x] += ssq [threadIdx.x + st];
        }
        __syncthreads();
    }
    if (threadIdx.x == 0) {
        float mean = ssum[0] * invM;
        float var  = ssq[0] * invM - mean*mean;
        float sc   = rsqrtf(var + 1e-5f) * g[o];
        g_scale[o] = sc;
        g_shift[o] = bta[o] - mean * sc;
    }
}

// ------ BN + LeakyReLU on maxed values; emits next h (fp32 + 3-way split) -----
__global__ void normedge_kernel(int OUT, int foff, float* __restrict__ hnext,
                                int wantnext) {
    __shared__ float sh[256];
    int p = blockIdx.x, o = threadIdx.x;
    float v = g_fused[(size_t)p*512 + foff + o] * g_scale[o] + g_shift[o];
    v = v > 0.f ? v : 0.2f*v;
    g_fused[(size_t)p*512 + foff + o] = v;
    float vo = __shfl_xor_sync(0xffffffffu, v, 1);
    if (wantnext) {
        hnext[(size_t)p*OUT + o] = v;
        if (!(o & 1)) {
            float h0, m0, l0, h1, m1, l1;
            split3(v,  h0, m0, l0);
            split3(vo, h1, m1, l1);
            size_t idx = (size_t)p*(OUT/2) + (o >> 1);
            g_hh[idx] = packbf2(h0, h1);
            g_hm[idx] = packbf2(m0, m1);
            g_hl[idx] = packbf2(l0, l1);
        }
    }
    sh[o] = v*v;
    __syncthreads();
    for (int st = OUT >> 1; st > 0; st >>= 1) {
        if (o < st) sh[o] += sh[o + st];
        __syncthreads();
    }
    if (o == 0 && wantnext) g_xx[p] = sh[0];
}

// ---------------- split Wf into bf16 hi/lo -------------------------------------
__global__ void wfsplit_kernel(const float* __restrict__ Wf) {
    int i = blockIdx.x*256 + threadIdx.x;
    if (i >= 1024*512) return;
    float w = Wf[i];
    __nv_bfloat16 h = __float2bfloat16(w);
    float r = w - __bfloat162float(h);
    g_bh[i] = h;
    g_bl[i] = __float2bfloat16(r);
}

// ---------------- final linear via HMMA bf16-split ----------------------------
__global__ void __launch_bounds__(256) finalmma_kernel(float* __restrict__ out) {
    __shared__ uint32_t sAh[128*18], sAl[128*18];
    __shared__ uint32_t sBh[128*18], sBl[128*18];
    __shared__ float red[2][2][128];

    int tid = threadIdx.x, wid = tid >> 5, lane = tid & 31;
    int g = lane >> 2, t = lane & 3;
    int wm = wid >> 2, wn = wid & 3;
    int pb = blockIdx.x, ob = blockIdx.y;
    int pbase = pb * 128, obase = ob * 128;

    float acc[4][4][4];
    #pragma unroll
    for (int mi = 0; mi < 4; mi++)
        #pragma unroll
        for (int ni = 0; ni < 4; ni++)
            #pragma unroll
            for (int j = 0; j < 4; j++) acc[mi][ni][j] = 0.f;

    const uint32_t* bh2 = (const uint32_t*)g_bh;
    const uint32_t* bl2 = (const uint32_t*)g_bl;

    for (int c0 = 0; c0 < 512; c0 += 32) {
        __syncthreads();
        #pragma unroll
        for (int i = tid; i < 2048; i += 256) {
            int row = i >> 4, kp = i & 15;
            float2 v = *(const float2*)&g_fused[(size_t)(pbase + row)*512 + c0 + kp*2];
            __nv_bfloat16 h0 = __float2bfloat16(v.x);
            __nv_bfloat16 h1 = __float2bfloat16(v.y);
            float r0 = v.x - __bfloat162float(h0);
            float r1 = v.y - __bfloat162float(h1);
            __nv_bfloat162 hp; hp.x = h0; hp.y = h1;
            sAh[row*18 + kp] = *(uint32_t*)&hp;
            sAl[row*18 + kp] = packbf2(r0, r1);
            size_t gi = (size_t)(obase + row)*256 + (c0 >> 1) + kp;
            sBh[row*18 + kp] = bh2[gi];
            sBl[row*18 + kp] = bl2[gi];
        }
        __syncthreads();
        #pragma unroll
        for (int ks = 0; ks < 2; ks++) {
            int kp0 = ks * 8;
            uint32_t ah[4][4], al[4][4];
            #pragma unroll
            for (int mi = 0; mi < 4; mi++) {
                int r = wm*64 + mi*16 + g;
                ah[mi][0] = sAh[r*18 + kp0 + t];
                ah[mi][1] = sAh[(r+8)*18 + kp0 + t];
                ah[mi][2] = sAh[r*18 + kp0 + 4 + t];
                ah[mi][3] = sAh[(r+8)*18 + kp0 + 4 + t];
                al[mi][0] = sAl[r*18 + kp0 + t];
                al[mi][1] = sAl[(r+8)*18 + kp0 + t];
                al[mi][2] = sAl[r*18 + kp0 + 4 + t];
                al[mi][3] = sAl[(r+8)*18 + kp0 + 4 + t];
            }
            uint32_t bh[4][2], bl[4][2];
            #pragma unroll
            for (int ni = 0; ni < 4; ni++) {
                int n = wn*32 + ni*8 + g;
                bh[ni][0] = sBh[n*18 + kp0 + t];
                bh[ni][1] = sBh[n*18 + kp0 + 4 + t];
                bl[ni][0] = sBl[n*18 + kp0 + t];
                bl[ni][1] = sBl[n*18 + kp0 + 4 + t];
            }
            #pragma unroll
            for (int mi = 0; mi < 4; mi++)
                #pragma unroll
                for (int ni = 0; ni < 4; ni++) {
                    mma16816(acc[mi][ni], ah[mi], bh[ni]);
                    mma16816(acc[mi][ni], ah[mi], bl[ni]);
                    mma16816(acc[mi][ni], al[mi], bh[ni]);
                }
        }
    }

    #pragma unroll
    for (int ni = 0; ni < 4; ni++) {
        float s0 = 0.f, s1 = 0.f, q0 = 0.f, q1 = 0.f;
        #pragma unroll
        for (int mi = 0; mi < 4; mi++) {
            float* a = acc[mi][ni];
            int row = pbase + wm*64 + mi*16 + g;
            int col = obase + wn*32 + ni*8 + t*2;
            *(float2*)&out[(size_t)row*1024 + col]     = make_float2(a[0], a[1]);
            *(float2*)&out[(size_t)(row+8)*1024 + col] = make_float2(a[2], a[3]);
            s0 += a[0] + a[2]; s1 += a[1] + a[3];
            q0 += a[0]*a[0] + a[2]*a[2];
            q1 += a[1]*a[1] + a[3]*a[3];
        }
        #pragma unroll
        for (int off = 4; off < 32; off <<= 1) {
            s0 += __shfl_xor_sync(0xffffffffu, s0, off);
            s1 += __shfl_xor_sync(0xffffffffu, s1, off);
            q0 += __shfl_xor_sync(0xffffffffu, q0, off);
            q1 += __shfl_xor_sync(0xffffffffu, q1, off);
        }
        if (g == 0) {
            int colw = wn*32 + ni*8 + t*2;
            red[wm][0][colw]   = s0;
            red[wm][0][colw+1] = s1;
            red[wm][1][colw]   = q0;
            red[wm][1][colw+1] = q1;
        }
    }
    __syncthreads();
    if (tid < 128) {
        float s = red[0][0][tid] + red[1][0][tid];
        float q = red[0][1][tid] + red[1][1][tid];
        g_psum[(size_t)(obase + tid)*64 + pb] = s;
        g_pssq[(size_t)(obase + tid)*64 + pb] = q;
    }
}

// ---------------- final BN + LeakyReLU in place --------------------------------
__global__ void normout_kernel(float* __restrict__ out) {
    int i = blockIdx.x*256 + threadIdx.x;
    if (i >= NP*1024) return;
    int o = i & 1023;
    float v = out[i] * g_scale[o] + g_shift[o];
    out[i] = v > 0.f ? v : 0.2f*v;
}

// ------------------------------- launcher -------------------------------------
extern "C" void kernel_launch(void* const* d_in, const int* in_sizes, int n_in,
                              void* d_out, int out_size) {
    (void)in_sizes; (void)n_in; (void)out_size;
    const float* x  = (const float*)d_in[0];
    const float* W[4]  = {(const float*)d_in[1],  (const float*)d_in[4],
                          (const float*)d_in[7],  (const float*)d_in[10]};
    const float* ga[4] = {(const float*)d_in[2],  (const float*)d_in[5],
                          (const float*)d_in[8],  (const float*)d_in[11]};
    const float* bt[4] = {(const float*)d_in[3],  (const float*)d_in[6],
                          (const float*)d_in[9],  (const float*)d_in[12]};
    const float* Wf = (const float*)d_in[13];
    const float* gf = (const float*)d_in[14];
    const float* bf = (const float*)d_in[15];
    float* out = (float*)d_out;

    float *h1, *h2;
    cudaGetSymbolAddress((void**)&h1, g_h1);
    cudaGetSymbolAddress((void**)&h2, g_h2);
    float* hn[2] = {h1, h2};

    const int Cs[4]     = {3, 64, 64, 128};
    const int Cps[4]    = {4, 64, 64, 128};
    const int C2s[4]    = {2, 32, 32, 64};
    const int OUTs[4]   = {64, 64, 128, 256};
    const int foffs[4]  = {0, 64, 128, 256};
    const int nkss[4]   = {1, 2, 2, 2};
    const int nchks[4]  = {1, 2, 2, 4};

    wfsplit_kernel<<<(1024*512 + 255)/256, 256>>>(Wf);
    xx_kernel<<<NP, 64>>>(x, 3);
    xsplit_kernel<<<(NP + 255)/256, 256>>>(x);

    const float* hcur = x;
    for (int i = 0; i < 4; i++) {
        int C = Cs[i], Cp = Cps[i], C2 = C2s[i], OUT = OUTs[i];
        negdist_kernel<<<dim3(NN/64, NN/64, BB), 256>>>(hcur, C);
        topk_kernel<<<NP/8, 256>>>();
        int wtot = (Cp/4)*OUT;
        wtrans_kernel<<<(wtot + 255)/256, 256>>>(W[i], C, Cp, OUT);
        wsplit_kernel<<<(OUT*C2 + 255)/256, 256>>>(W[i], C, C2, OUT);
        base_kernel<<<NP, OUT, Cp*sizeof(float)>>>(hcur, C, Cp, OUT);
        if (i < 3) {
            // hi-precision (feeds next KNN): NI=2 tiles
            edgemma_kernel<2, true><<<dim3(NP/4, OUT/64), 256>>>(
                C2, OUT, foffs[i], nkss[i], nchks[i]);
        } else {
            // last edge layer: cheap 2-way split
            edgemma_kernel<4, false><<<dim3(NP/4, OUT/128), 256>>>(
                C2, OUT, foffs[i], nkss[i], nchks[i]);
        }
        chanstats_kernel<<<OUT, 256>>>(ga[i], bt[i], NP, 1.f/((float)NP*KK));
        normedge_kernel<<<NP, OUT>>>(OUT, foffs[i], hn[i & 1], (i < 3) ? 1 : 0);
        hcur = hn[i & 1];
    }

    finalmma_kernel<<<dim3(64, 8), 256>>>(out);
    chanstats_kernel<<<1024, 256>>>(gf, bf, 64, 1.f/(float)NP);
    normout_kernel<<<(NP*1024 + 255)/256, 256>>>(out);
}

// round 8
// speedup vs baseline: 1.1716x; 1.1716x over previous
#include <cuda_runtime.h>
#include <cuda_bf16.h>
#include <cstdint>

#define BB 8
#define NN 1024
#define NP (BB*NN)
#define KK 20

// ---------------- scratch (device globals; no allocation allowed) -------------
__device__ float g_h1[NP*256];
__device__ float g_h2[NP*256];
__device__ float g_dist[(size_t)BB*NN*NN];
__device__ int   g_idx[NP*KK];
__device__ float g_xx[NP];
__device__ ulonglong2 g_w1p[131072];         // fp32-packed W1 pairs [c4*OUT+o]
__device__ float4     g_wdp[8192];           // packed (W2 - W1), [c4][OUT]
__device__ uint32_t g_wh[256*64];            // W1 split hi (L3), [o][c2] bf16x2
__device__ uint32_t g_wm[256*64];            // W1 split lo (L3)
__device__ uint32_t g_hh[NP*64];             // h split hi (L2 out), [p][c2]
__device__ uint32_t g_hm[NP*64];             // h split lo
__device__ float g_base[(size_t)NP*256];     // (W2-W1)*ctr per (p,o), L3
__device__ float g_fused[(size_t)NP*512];
__device__ float g_psum[(size_t)NP*256];     // transposed: [o*P + p]
__device__ float g_pssq[(size_t)NP*256];
__device__ float g_scale[1024];
__device__ float g_shift[1024];
__device__ __nv_bfloat16 g_bh[1024*512];     // Wf split hi
__device__ __nv_bfloat16 g_bl[1024*512];     // Wf split lo

__device__ __forceinline__ void fma2(unsigned long long& d,
                                     unsigned long long a, unsigned long long b) {
    asm("fma.rn.f32x2 %0, %1, %2, %0;" : "+l"(d) : "l"(a), "l"(b));
}
__device__ __forceinline__ unsigned long long pack2(float lo, float hi) {
    unsigned long long r;
    asm("mov.b64 %0, {%1, %2};" : "=l"(r) : "f"(lo), "f"(hi));
    return r;
}
__device__ __forceinline__ void unpack2(float& lo, float& hi, unsigned long long v) {
    asm("mov.b64 {%0, %1}, %2;" : "=f"(lo), "=f"(hi) : "l"(v));
}
__device__ __forceinline__ uint32_t packbf2(float a, float b) {
    __nv_bfloat162 p;
    p.x = __float2bfloat16(a);
    p.y = __float2bfloat16(b);
    return *(uint32_t*)&p;
}
// HMMA m16n8k16 bf16 -> fp32 accumulate
__device__ __forceinline__ void mma16816(float* c, const uint32_t* a, const uint32_t* b) {
    asm volatile("mma.sync.aligned.m16n8k16.row.col.f32.bf16.bf16.f32 "
        "{%0,%1,%2,%3}, {%4,%5,%6,%7}, {%8,%9}, {%0,%1,%2,%3};"
        : "+f"(c[0]), "+f"(c[1]), "+f"(c[2]), "+f"(c[3])
        : "r"(a[0]), "r"(a[1]), "r"(a[2]), "r"(a[3]), "r"(b[0]), "r"(b[1]));
}

// ---------------- ||x||^2 per point (input layer only) -------------------------
__global__ void xx_kernel(const float* __restrict__ h, int C) {
    int p = blockIdx.x;
    __shared__ float sh[64];
    float s = 0.f;
    for (int c = threadIdx.x; c < C; c += 64) {
        float v = h[(size_t)p*C + c];
        s += v*v;
    }
    sh[threadIdx.x] = s; __syncthreads();
    for (int st = 32; st > 0; st >>= 1) {
        if (threadIdx.x < st) sh[threadIdx.x] += sh[threadIdx.x + st];
        __syncthreads();
    }
    if (threadIdx.x == 0) g_xx[p] = sh[0];
}

// ---------------- neg_dist: 64x64 register-tiled GEMM + f32x2 ------------------
__global__ void __launch_bounds__(256) negdist_kernel(const float* __restrict__ h, int C) {
    __shared__ float As[16][68];
    __shared__ float Bs[16][68];
    int b  = blockIdx.z;
    int n0 = blockIdx.y * 64, m0 = blockIdx.x * 64;
    int tid = threadIdx.x;
    int tx = tid & 15, ty = tid >> 4;
    unsigned long long acc[4][2];
    #pragma unroll
    for (int i = 0; i < 4; i++) { acc[i][0] = 0ull; acc[i][1] = 0ull; }

    for (int c0 = 0; c0 < C; c0 += 16) {
        #pragma unroll
        for (int r = 0; r < 4; r++) {
            int idx = tid + r*256;
            int cc = idx & 15, n = idx >> 4;
            int c = c0 + cc;
            As[cc][n] = (c < C) ? h[((size_t)(b*NN) + n0 + n)*C + c] : 0.f;
            Bs[cc][n] = (c < C) ? h[((size_t)(b*NN) + m0 + n)*C + c] : 0.f;
        }
        __syncthreads();
        #pragma unroll
        for (int kk = 0; kk < 16; kk++) {
            float4 a = *(const float4*)&As[kk][ty*4];
            ulonglong2 bb = *(const ulonglong2*)&Bs[kk][tx*4];
            unsigned long long a0 = pack2(a.x, a.x);
            unsigned long long a1 = pack2(a.y, a.y);
            unsigned long long a2 = pack2(a.z, a.z);
            unsigned long long a3 = pack2(a.w, a.w);
            fma2(acc[0][0], a0, bb.x); fma2(acc[0][1], a0, bb.y);
            fma2(acc[1][0], a1, bb.x); fma2(acc[1][1], a1, bb.y);
            fma2(acc[2][0], a2, bb.x); fma2(acc[2][1], a2, bb.y);
            fma2(acc[3][0], a3, bb.x); fma2(acc[3][1], a3, bb.y);
        }
        __syncthreads();
    }
    #pragma unroll
    for (int i = 0; i < 4; i++) {
        int n = n0 + ty*4 + i;
        float xn = g_xx[b*NN + n];
        #pragma unroll
        for (int jp = 0; jp < 2; jp++) {
            float lo, hi;
            unpack2(lo, hi, acc[i][jp]);
            int m = m0 + tx*4 + jp*2;
            g_dist[((size_t)(b*NN) + n)*NN + m]     = 2.f*lo - xn - g_xx[b*NN + m];
            g_dist[((size_t)(b*NN) + n)*NN + m + 1] = 2.f*hi - xn - g_xx[b*NN + m + 1];
        }
    }
}

// ------- top-k: warp per point, lazy per-lane top-2 (exact, tie by index) ------
__global__ void topk_kernel() {
    int lane = threadIdx.x & 31;
    int p = blockIdx.x * 8 + (threadIdx.x >> 5);
    const float* row = g_dist + (size_t)p*NN;
    float v[32];
    #pragma unroll
    for (int j = 0; j < 32; j++) v[j] = row[j*32 + lane];

    // initial per-lane top-2 (strict >: earliest index kept on ties)
    float m1 = -1e30f, m2 = -1e30f; int i1 = 0, i2 = 0;
    #pragma unroll
    for (int j = 0; j < 32; j++) {
        float x = v[j];
        if (x > m1) { m2 = m1; i2 = i1; m1 = x; i1 = j; }
        else if (x > m2) { m2 = x; i2 = j; }
    }
    bool have2 = true;

    for (int k = 0; k < KK; k++) {
        float bv = m1; int gi = i1*32 + lane;
        #pragma unroll
        for (int off = 16; off > 0; off >>= 1) {
            float ov = __shfl_xor_sync(0xffffffffu, bv, off);
            int   og = __shfl_xor_sync(0xffffffffu, gi, off);
            if (ov > bv || (ov == bv && og < gi)) { bv = ov; gi = og; }
        }
        if (lane == 0) g_idx[p*KK + k] = gi;
        if (lane == (gi & 31)) {
            v[i1] = -1e30f;
            if (have2) { m1 = m2; i1 = i2; have2 = false; }
            else {
                float a = -1e30f, b2 = -1e30f; int ai = 0, bi = 0;
                #pragma unroll
                for (int j = 0; j < 32; j++) {
                    float x = v[j];
                    if (x > a) { b2 = a; bi = ai; a = x; ai = j; }
                    else if (x > b2) { b2 = x; bi = j; }
                }
                m1 = a; i1 = ai; m2 = b2; i2 = bi; have2 = true;
            }
        }
    }
}

// ------- weight transform: W(out,2C) -> fp32 packed W1 pairs + Wd -------------
__global__ void wtrans_kernel(const float* __restrict__ W, int C, int Cp, int OUT) {
    int i = blockIdx.x*256 + threadIdx.x;
    int total = (Cp >> 2) * OUT;
    if (i >= total) return;
    int o = i % OUT;
    int c4 = i / OUT;
    float w1[4], wd[4];
    #pragma unroll
    for (int j = 0; j < 4; j++) {
        int c = c4*4 + j;
        if (c < C) {
            float a = W[(size_t)o*2*C + c];
            float b2 = W[(size_t)o*2*C + C + c];
            w1[j] = a; wd[j] = b2 - a;
        } else { w1[j] = 0.f; wd[j] = 0.f; }
    }
    ulonglong2 wp;
    wp.x = pack2(w1[0], w1[1]);
    wp.y = pack2(w1[2], w1[3]);
    g_w1p[i] = wp;
    g_wdp[i] = make_float4(wd[0], wd[1], wd[2], wd[3]);
}

// ------- W1 2-way split (L3 only): W(out,2C) -> g_wh/g_wm [o][c2] -------------
__global__ void wsplit_kernel(const float* __restrict__ W, int C, int C2, int OUT) {
    int i = blockIdx.x*256 + threadIdx.x;
    if (i >= OUT*C2) return;
    int o = i / C2, c2 = i - o*C2;
    float w0 = W[(size_t)o*2*C + 2*c2];
    float w1 = (2*c2 + 1 < C) ? W[(size_t)o*2*C + 2*c2 + 1] : 0.f;
    __nv_bfloat16 h0 = __float2bfloat16(w0);
    __nv_bfloat16 h1 = __float2bfloat16(w1);
    g_wh[i] = ((uint32_t)*(uint16_t*)&h1 << 16) | (uint32_t)*(uint16_t*)&h0;
    g_wm[i] = packbf2(w0 - __bfloat162float(h0), w1 - __bfloat162float(h1));
}

// ------- base = (W2-W1)*ctr per (p,o)  (L3 only) -------------------------------
__global__ void base_kernel(const float* __restrict__ h, int C, int Cp, int OUT) {
    extern __shared__ float ctr[];
    int p = blockIdx.x, o = threadIdx.x;
    for (int c = o; c < Cp; c += OUT)
        ctr[c] = (c < C) ? h[(size_t)p*C + c] : 0.f;
    __syncthreads();
    int C4 = Cp >> 2;
    const float4* c4p = (const float4*)ctr;
    float s = 0.f;
    for (int c4 = 0; c4 < C4; c4++) {
        float4 w = g_wdp[c4*OUT + o];
        float4 cv = c4p[c4];
        s += w.x*cv.x + w.y*cv.y + w.z*cv.z + w.w*cv.w;
    }
    g_base[(size_t)p*OUT + o] = s;
}

// ------- edge conv (layers 0-2): exact fp32, 2 outputs/thread, f32x2 ----------
__global__ void edgeconv_kernel(const float* __restrict__ h, int C, int Cp,
                                int lc, int OUT, int foff) {
    extern __shared__ float sm[];
    float* ctr  = sm;
    float* feat = sm + Cp;
    __shared__ int nb[32];
    int p   = blockIdx.x;
    int tid = threadIdx.x;
    int HALF = blockDim.x;
    int b   = p >> 10;
    if (tid < KK) nb[tid] = g_idx[p*KK + tid];
    for (int c = tid; c < Cp; c += HALF)
        ctr[c] = (c < C) ? h[(size_t)p*C + c] : 0.f;
    __syncthreads();
    int mask = Cp - 1;
    for (int t = tid; t < KK*Cp; t += HALF) {
        int k = t >> lc, c = t & mask;
        feat[t] = (c < C) ? h[((size_t)((b << 10) + nb[k]))*C + c] : 0.f;
    }
    __syncthreads();

    int o0 = tid, o1 = tid + HALF;
    int C4 = Cp >> 2;
    const float4* c4p = (const float4*)ctr;
    float base0 = 0.f, base1 = 0.f;
    for (int c4 = 0; c4 < C4; c4++) {
        float4 cv = c4p[c4];
        float4 w0 = g_wdp[c4*OUT + o0];
        float4 w1 = g_wdp[c4*OUT + o1];
        base0 += w0.x*cv.x + w0.y*cv.y + w0.z*cv.z + w0.w*cv.w;
        base1 += w1.x*cv.x + w1.y*cv.y + w1.z*cv.z + w1.w*cv.w;
    }
    const ulonglong2* f2 = (const ulonglong2*)feat;
    float mx0=-1e30f, s0=0.f, q0=0.f;
    float mx1=-1e30f, s1=0.f, q1=0.f;
    #pragma unroll
    for (int kc = 0; kc < KK; kc += 10) {
        unsigned long long a0[10], a1[10];
        #pragma unroll
        for (int k = 0; k < 10; k++) { a0[k] = 0ull; a1[k] = 0ull; }
        for (int c4 = 0; c4 < C4; c4++) {
            ulonglong2 w0 = g_w1p[c4*OUT + o0];
            ulonglong2 w1 = g_w1p[c4*OUT + o1];
            #pragma unroll
            for (int k = 0; k < 10; k++) {
                ulonglong2 fv = f2[(kc+k)*C4 + c4];
                fma2(a0[k], w0.x, fv.x); fma2(a0[k], w0.y, fv.y);
                fma2(a1[k], w1.x, fv.x); fma2(a1[k], w1.y, fv.y);
            }
        }
        #pragma unroll
        for (int k = 0; k < 10; k++) {
            float lo, hi;
            unpack2(lo, hi, a0[k]);
            float y = base0 + lo + hi;
            mx0 = fmaxf(mx0, y); s0 += y; q0 += y*y;
            unpack2(lo, hi, a1[k]);
            y = base1 + lo + hi;
            mx1 = fmaxf(mx1, y); s1 += y; q1 += y*y;
        }
    }
    g_fused[(size_t)p*512 + foff + o0] = mx0;
    g_fused[(size_t)p*512 + foff + o1] = mx1;
    g_psum[(size_t)o0*NP + p] = s0; g_pssq[(size_t)o0*NP + p] = q0;
    g_psum[(size_t)o1*NP + p] = s1; g_pssq[(size_t)o1*NP + p] = q1;
}

// ------- edge conv L3 via HMMA 2-way bf16 split (3 products) ------------------
// Block: 4 points (128 A rows = 4 x 32 padded k), 128 output cols; grid (NP/4, 2)
__global__ void __launch_bounds__(256) edgemma_kernel(
    int C2, int OUT, int foff, int nchunks)
{
    __shared__ uint32_t sA[2][128*18];
    __shared__ uint32_t sB[2][128*18];
    __shared__ int nb[80];

    int tid = threadIdx.x, wid = tid >> 5, lane = tid & 31;
    int g = lane >> 2, t = lane & 3;
    int wm = wid >> 2, wn = wid & 3;
    int pbase = blockIdx.x * 4;
    int obase = blockIdx.y * 128;
    int batch_off = (pbase >> 10) << 10;

    if (tid < 80) nb[tid] = g_idx[(pbase + tid/20)*KK + (tid - (tid/20)*20)];

    float acc[4][4][4];
    #pragma unroll
    for (int mi = 0; mi < 4; mi++)
        #pragma unroll
        for (int ni = 0; ni < 4; ni++)
            #pragma unroll
            for (int j = 0; j < 4; j++) acc[mi][ni][j] = 0.f;

    __syncthreads();

    for (int chunk = 0; chunk < nchunks; chunk++) {
        if (chunk > 0) __syncthreads();
        // A fill: 128 rows x 16 k-pairs (gathered neighbor features)
        for (int i = tid; i < 2048; i += 256) {
            int row = i >> 4, kp = i & 15;
            int k = row & 31, lp = row >> 5;
            int c2 = chunk*16 + kp;
            bool ok = (k < KK && c2 < C2);
            size_t idx = ok ? (size_t)(batch_off + nb[lp*20 + k])*C2 + c2 : 0;
            sA[0][row*18 + kp] = ok ? g_hh[idx] : 0u;
            sA[1][row*18 + kp] = ok ? g_hm[idx] : 0u;
        }
        // B fill: 128 weight rows x 16 k-pairs
        for (int i = tid; i < 2048; i += 256) {
            int row = i >> 4, kp = i & 15;
            int c2 = chunk*16 + kp;
            bool ok = (c2 < C2);
            size_t idx = ok ? (size_t)(obase + row)*C2 + c2 : 0;
            sB[0][row*18 + kp] = ok ? g_wh[idx] : 0u;
            sB[1][row*18 + kp] = ok ? g_wm[idx] : 0u;
        }
        __syncthreads();
        #pragma unroll
        for (int ks = 0; ks < 2; ks++) {
            int kp0 = ks * 8;
            uint32_t af[2][4][4];
            #pragma unroll
            for (int a = 0; a < 2; a++)
                #pragma unroll
                for (int mi = 0; mi < 4; mi++) {
                    int r = wm*64 + mi*16 + g;
                    af[a][mi][0] = sA[a][r*18 + kp0 + t];
                    af[a][mi][1] = sA[a][(r+8)*18 + kp0 + t];
                    af[a][mi][2] = sA[a][r*18 + kp0 + 4 + t];
                    af[a][mi][3] = sA[a][(r+8)*18 + kp0 + 4 + t];
                }
            uint32_t bf[2][4][2];
            #pragma unroll
            for (int a = 0; a < 2; a++)
                #pragma unroll
                for (int ni = 0; ni < 4; ni++) {
                    int n = wn*32 + ni*8 + g;
                    bf[a][ni][0] = sB[a][n*18 + kp0 + t];
                    bf[a][ni][1] = sB[a][n*18 + kp0 + 4 + t];
                }
            #pragma unroll
            for (int mi = 0; mi < 4; mi++)
                #pragma unroll
                for (int ni = 0; ni < 4; ni++) {
                    mma16816(acc[mi][ni], af[0][mi], bf[0][ni]);
                    mma16816(acc[mi][ni], af[0][mi], bf[1][ni]);
                    mma16816(acc[mi][ni], af[1][mi], bf[0][ni]);
                }
        }
    }

    // epilogue: per-point max / sum / sumsq over valid k rows
    #pragma unroll
    for (int half = 0; half < 2; half++) {
        int p = pbase + wm*2 + half;
        #pragma unroll
        for (int ni = 0; ni < 4; ni++) {
            #pragma unroll
            for (int j = 0; j < 2; j++) {
                float v0 = acc[half*2][ni][j];       // k = g
                float v1 = acc[half*2][ni][j+2];     // k = g+8
                float v2 = acc[half*2+1][ni][j];     // k = 16+g (valid g<4)
                bool ok2 = (g < 4);
                float mx = fmaxf(v0, v1);
                if (ok2) mx = fmaxf(mx, v2);
                float s = v0 + v1 + (ok2 ? v2 : 0.f);
                float q = v0*v0 + v1*v1 + (ok2 ? v2*v2 : 0.f);
                #pragma unroll
                for (int off = 4; off <= 16; off <<= 1) {
                    mx = fmaxf(mx, __shfl_xor_sync(0xffffffffu, mx, off));
                    s += __shfl_xor_sync(0xffffffffu, s, off);
                    q += __shfl_xor_sync(0xffffffffu, q, off);
                }
                if (g == 0) {
                    int o = obase + wn*32 + ni*8 + t*2 + j;
                    float b = g_base[(size_t)p*OUT + o];
                    g_fused[(size_t)p*512 + foff + o] = mx + b;
                    g_psum[(size_t)o*NP + p] = s + 20.f*b;
                    g_pssq[(size_t)o*NP + p] = q + 2.f*b*s + 20.f*b*b;
                }
            }
        }
    }
}

// ---------------- per-channel BN stats (coalesced, deterministic) -------------
__global__ void chanstats_kernel(const float* __restrict__ g,
                                 const float* __restrict__ bta,
                                 int P, float invM) {
    int o = blockIdx.x;
    __shared__ float ssum[256], ssq[256];
    const float* ps = g_psum + (size_t)o*P;
    const float* pq = g_pssq + (size_t)o*P;
    float s = 0.f, q = 0.f;
    for (int i = threadIdx.x; i < P; i += 256) { s += ps[i]; q += pq[i]; }
    ssum[threadIdx.x] = s; ssq[threadIdx.x] = q;
    __syncthreads();
    for (int st = 128; st > 0; st >>= 1) {
        if (threadIdx.x < st) {
            ssum[threadIdx.x] += ssum[threadIdx.x + st];
            ssq [threadIdx.x] += ssq [threadIdx.x + st];
        }
        __syncthreads();
    }
    if (threadIdx.x == 0) {
        float mean = ssum[0] * invM;
        float var  = ssq[0] * invM - mean*mean;
        float sc   = rsqrtf(var + 1e-5f) * g[o];
        g_scale[o] = sc;
        g_shift[o] = bta[o] - mean * sc;
    }
}

// -- BN + LeakyReLU; optional fp32 hnext + ||h||^2; optional 2-way bf16 split --
__global__ void normedge_kernel(int OUT, int foff, float* __restrict__ hnext,
                                int wantnext, int wantsplit) {
    __shared__ float sh[256];
    int p = blockIdx.x, o = threadIdx.x;
    float v = g_fused[(size_t)p*512 + foff + o] * g_scale[o] + g_shift[o];
    v = v > 0.f ? v : 0.2f*v;
    g_fused[(size_t)p*512 + foff + o] = v;
    float vo = __shfl_xor_sync(0xffffffffu, v, 1);
    if (wantnext) hnext[(size_t)p*OUT + o] = v;
    if (wantsplit && !(o & 1)) {
        __nv_bfloat16 h0 = __float2bfloat16(v);
        __nv_bfloat16 h1 = __float2bfloat16(vo);
        size_t idx = (size_t)p*(OUT/2) + (o >> 1);
        g_hh[idx] = ((uint32_t)*(uint16_t*)&h1 << 16) | (uint32_t)*(uint16_t*)&h0;
        g_hm[idx] = packbf2(v - __bfloat162float(h0), vo - __bfloat162float(h1));
    }
    sh[o] = v*v;
    __syncthreads();
    for (int st = OUT >> 1; st > 0; st >>= 1) {
        if (o < st) sh[o] += sh[o + st];
        __syncthreads();
    }
    if (o == 0 && wantnext) g_xx[p] = sh[0];
}

// ---------------- split Wf into bf16 hi/lo -------------------------------------
__global__ void wfsplit_kernel(const float* __restrict__ Wf) {
    int i = blockIdx.x*256 + threadIdx.x;
    if (i >= 1024*512) return;
    float w = Wf[i];
    __nv_bfloat16 h = __float2bfloat16(w);
    float r = w - __bfloat162float(h);
    g_bh[i] = h;
    g_bl[i] = __float2bfloat16(r);
}

// ---------------- final linear via HMMA bf16-split ----------------------------
__global__ void __launch_bounds__(256) finalmma_kernel(float* __restrict__ out) {
    __shared__ uint32_t sAh[128*18], sAl[128*18];
    __shared__ uint32_t sBh[128*18], sBl[128*18];
    __shared__ float red[2][2][128];

    int tid = threadIdx.x, wid = tid >> 5, lane = tid & 31;
    int g = lane >> 2, t = lane & 3;
    int wm = wid >> 2, wn = wid & 3;
    int pb = blockIdx.x, ob = blockIdx.y;
    int pbase = pb * 128, obase = ob * 128;

    float acc[4][4][4];
    #pragma unroll
    for (int mi = 0; mi < 4; mi++)
        #pragma unroll
        for (int ni = 0; ni < 4; ni++)
            #pragma unroll
            for (int j = 0; j < 4; j++) acc[mi][ni][j] = 0.f;

    const uint32_t* bh2 = (const uint32_t*)g_bh;
    const uint32_t* bl2 = (const uint32_t*)g_bl;

    for (int c0 = 0; c0 < 512; c0 += 32) {
        __syncthreads();
        #pragma unroll
        for (int i = tid; i < 2048; i += 256) {
            int row = i >> 4, kp = i & 15;
            float2 v = *(const float2*)&g_fused[(size_t)(pbase + row)*512 + c0 + kp*2];
            __nv_bfloat16 h0 = __float2bfloat16(v.x);
            __nv_bfloat16 h1 = __float2bfloat16(v.y);
            float r0 = v.x - __bfloat162float(h0);
            float r1 = v.y - __bfloat162float(h1);
            __nv_bfloat162 hp; hp.x = h0; hp.y = h1;
            sAh[row*18 + kp] = *(uint32_t*)&hp;
            sAl[row*18 + kp] = packbf2(r0, r1);
            size_t gi = (size_t)(obase + row)*256 + (c0 >> 1) + kp;
            sBh[row*18 + kp] = bh2[gi];
            sBl[row*18 + kp] = bl2[gi];
        }
        __syncthreads();
        #pragma unroll
        for (int ks = 0; ks < 2; ks++) {
            int kp0 = ks * 8;
            uint32_t ah[4][4], al[4][4];
            #pragma unroll
            for (int mi = 0; mi < 4; mi++) {
                int r = wm*64 + mi*16 + g;
                ah[mi][0] = sAh[r*18 + kp0 + t];
                ah[mi][1] = sAh[(r+8)*18 + kp0 + t];
                ah[mi][2] = sAh[r*18 + kp0 + 4 + t];
                ah[mi][3] = sAh[(r+8)*18 + kp0 + 4 + t];
                al[mi][0] = sAl[r*18 + kp0 + t];
                al[mi][1] = sAl[(r+8)*18 + kp0 + t];
                al[mi][2] = sAl[r*18 + kp0 + 4 + t];
                al[mi][3] = sAl[(r+8)*18 + kp0 + 4 + t];
            }
            uint32_t bh[4][2], bl[4][2];
            #pragma unroll
            for (int ni = 0; ni < 4; ni++) {
                int n = wn*32 + ni*8 + g;
                bh[ni][0] = sBh[n*18 + kp0 + t];
                bh[ni][1] = sBh[n*18 + kp0 + 4 + t];
                bl[ni][0] = sBl[n*18 + kp0 + t];
                bl[ni][1] = sBl[n*18 + kp0 + 4 + t];
            }
            #pragma unroll
            for (int mi = 0; mi < 4; mi++)
                #pragma unroll
                for (int ni = 0; ni < 4; ni++) {
                    mma16816(acc[mi][ni], ah[mi], bh[ni]);
                    mma16816(acc[mi][ni], ah[mi], bl[ni]);
                    mma16816(acc[mi][ni], al[mi], bh[ni]);
                }
        }
    }

    #pragma unroll
    for (int ni = 0; ni < 4; ni++) {
        float s0 = 0.f, s1 = 0.f, q0 = 0.f, q1 = 0.f;
        #pragma unroll
        for (int mi = 0; mi < 4; mi++) {
            float* a = acc[mi][ni];
            int row = pbase + wm*64 + mi*16 + g;
            int col = obase + wn*32 + ni*8 + t*2;
            *(float2*)&out[(size_t)row*1024 + col]     = make_float2(a[0], a[1]);
            *(float2*)&out[(size_t)(row+8)*1024 + col] = make_float2(a[2], a[3]);
            s0 += a[0] + a[2]; s1 += a[1] + a[3];
            q0 += a[0]*a[0] + a[2]*a[2];
            q1 += a[1]*a[1] + a[3]*a[3];
        }
        #pragma unroll
        for (int off = 4; off < 32; off <<= 1) {
            s0 += __shfl_xor_sync(0xffffffffu, s0, off);
            s1 += __shfl_xor_sync(0xffffffffu, s1, off);
            q0 += __shfl_xor_sync(0xffffffffu, q0, off);
            q1 += __shfl_xor_sync(0xffffffffu, q1, off);
        }
        if (g == 0) {
            int colw = wn*32 + ni*8 + t*2;
            red[wm][0][colw]   = s0;
            red[wm][0][colw+1] = s1;
            red[wm][1][colw]   = q0;
            red[wm][1][colw+1] = q1;
        }
    }
    __syncthreads();
    if (tid < 128) {
        float s = red[0][0][tid] + red[1][0][tid];
        float q = red[0][1][tid] + red[1][1][tid];
        g_psum[(size_t)(obase + tid)*64 + pb] = s;
        g_pssq[(size_t)(obase + tid)*64 + pb] = q;
    }
}

// ---------------- final BN + LeakyReLU in place --------------------------------
__global__ void normout_kernel(float* __restrict__ out) {
    int i = blockIdx.x*256 + threadIdx.x;
    if (i >= NP*1024) return;
    int o = i & 1023;
    float v = out[i] * g_scale[o] + g_shift[o];
    out[i] = v > 0.f ? v : 0.2f*v;
}

// ------------------------------- launcher -------------------------------------
extern "C" void kernel_launch(void* const* d_in, const int* in_sizes, int n_in,
                              void* d_out, int out_size) {
    (void)in_sizes; (void)n_in; (void)out_size;
    const float* x  = (const float*)d_in[0];
    const float* W[4]  = {(const float*)d_in[1],  (const float*)d_in[4],
                          (const float*)d_in[7],  (const float*)d_in[10]};
    const float* ga[4] = {(const float*)d_in[2],  (const float*)d_in[5],
                          (const float*)d_in[8],  (const float*)d_in[11]};
    const float* bt[4] = {(const float*)d_in[3],  (const float*)d_in[6],
                          (const float*)d_in[9],  (const float*)d_in[12]};
    const float* Wf = (const float*)d_in[13];
    const float* gf = (const float*)d_in[14];
    const float* bf = (const float*)d_in[15];
    float* out = (float*)d_out;

    float *h1, *h2;
    cudaGetSymbolAddress((void**)&h1, g_h1);
    cudaGetSymbolAddress((void**)&h2, g_h2);
    float* hn[2] = {h1, h2};

    const int Cs[4]     = {3, 64, 64, 128};
    const int Cps[4]    = {4, 64, 64, 128};
    const int lcs[4]    = {2, 6, 6, 7};
    const int OUTs[4]   = {64, 64, 128, 256};
    const int foffs[4]  = {0, 64, 128, 256};

    wfsplit_kernel<<<(1024*512 + 255)/256, 256>>>(Wf);
    xx_kernel<<<NP, 64>>>(x, 3);

    const float* hcur = x;
    for (int i = 0; i < 4; i++) {
        int C = Cs[i], Cp = Cps[i], OUT = OUTs[i];
        negdist_kernel<<<dim3(NN/64, NN/64, BB), 256>>>(hcur, C);
        topk_kernel<<<NP/8, 256>>>();
        int wtot = (Cp/4)*OUT;
        wtrans_kernel<<<(wtot + 255)/256, 256>>>(W[i], C, Cp, OUT);
        if (i < 3) {
            // exact fp32 path (h bits identical to verified R5 run -> no KNN flips)
            size_t smem = (size_t)(Cp + KK*Cp) * sizeof(float);
            edgeconv_kernel<<<NP, OUT/2, smem>>>(hcur, C, Cp, lcs[i], OUT, foffs[i]);
        } else {
            // last edge layer: HMMA 2-way split (output never feeds KNN)
            int C2 = C/2;
            wsplit_kernel<<<(OUT*C2 + 255)/256, 256>>>(W[i], C, C2, OUT);
            base_kernel<<<NP, OUT, Cp*sizeof(float)>>>(hcur, C, Cp, OUT);
            edgemma_kernel<<<dim3(NP/4, 2), 256>>>(C2, OUT, foffs[i], C2/16);
        }
        chanstats_kernel<<<OUT, 256>>>(ga[i], bt[i], NP, 1.f/((float)NP*KK));
        int wantnext = (i < 3) ? 1 : 0;
        int wantsplit = (i == 2) ? 1 : 0;
        normedge_kernel<<<NP, OUT>>>(OUT, foffs[i], hn[i & 1], wantnext, wantsplit);
        hcur = hn[i & 1];
    }

    finalmma_kernel<<<dim3(64, 8), 256>>>(out);
    chanstats_kernel<<<1024, 256>>>(gf, bf, 64, 1.f/(float)NP);
    normout_kernel<<<(NP*1024 + 255)/256, 256>>>(out);
}

// round 9
// speedup vs baseline: 1.2121x; 1.0346x over previous
#include <cuda_runtime.h>
#include <cuda_bf16.h>
#include <cstdint>

#define BB 8
#define NN 1024
#define NP (BB*NN)
#define KK 20

// ---------------- scratch (device globals; no allocation allowed) -------------
__device__ float g_h1[NP*256];
__device__ float g_h2[NP*256];
__device__ float g_dist[(size_t)BB*NN*NN];
__device__ int   g_idx[NP*KK];
__device__ float g_xx[NP];
__device__ ulonglong2 g_w1p[131072];         // fp32-packed W1 pairs [c4*OUT+o]
__device__ float4     g_wdp[8192];           // packed (W2 - W1), [c4][OUT]
__device__ uint2 g_wp2[256*64];              // W1 split (hi,lo) L3, [o][c2]
__device__ uint2 g_hp[NP*64];                // h split (hi,lo) L2-out, [p][c2]
__device__ float g_base[(size_t)NP*256];     // (W2-W1)*ctr per (p,o), L3
__device__ float g_fused[(size_t)NP*512];
__device__ float g_psum[(size_t)NP*256];     // transposed: [o*P + p]
__device__ float g_pssq[(size_t)NP*256];
__device__ float g_scale[1024];
__device__ float g_shift[1024];
__device__ __nv_bfloat16 g_bh[1024*512];     // Wf split hi
__device__ __nv_bfloat16 g_bl[1024*512];     // Wf split lo

__device__ __forceinline__ void fma2(unsigned long long& d,
                                     unsigned long long a, unsigned long long b) {
    asm("fma.rn.f32x2 %0, %1, %2, %0;" : "+l"(d) : "l"(a), "l"(b));
}
__device__ __forceinline__ unsigned long long pack2(float lo, float hi) {
    unsigned long long r;
    asm("mov.b64 %0, {%1, %2};" : "=l"(r) : "f"(lo), "f"(hi));
    return r;
}
__device__ __forceinline__ void unpack2(float& lo, float& hi, unsigned long long v) {
    asm("mov.b64 {%0, %1}, %2;" : "=f"(lo), "=f"(hi) : "l"(v));
}
__device__ __forceinline__ uint32_t packbf2(float a, float b) {
    __nv_bfloat162 p;
    p.x = __float2bfloat16(a);
    p.y = __float2bfloat16(b);
    return *(uint32_t*)&p;
}
// HMMA m16n8k16 bf16 -> fp32 accumulate
__device__ __forceinline__ void mma16816(float* c, const uint32_t* a, const uint32_t* b) {
    asm volatile("mma.sync.aligned.m16n8k16.row.col.f32.bf16.bf16.f32 "
        "{%0,%1,%2,%3}, {%4,%5,%6,%7}, {%8,%9}, {%0,%1,%2,%3};"
        : "+f"(c[0]), "+f"(c[1]), "+f"(c[2]), "+f"(c[3])
        : "r"(a[0]), "r"(a[1]), "r"(a[2]), "r"(a[3]), "r"(b[0]), "r"(b[1]));
}

// ---------------- ||x||^2 per point (input layer only) -------------------------
__global__ void xx_kernel(const float* __restrict__ h, int C) {
    int p = blockIdx.x;
    __shared__ float sh[64];
    float s = 0.f;
    for (int c = threadIdx.x; c < C; c += 64) {
        float v = h[(size_t)p*C + c];
        s += v*v;
    }
    sh[threadIdx.x] = s; __syncthreads();
    for (int st = 32; st > 0; st >>= 1) {
        if (threadIdx.x < st) sh[threadIdx.x] += sh[threadIdx.x + st];
        __syncthreads();
    }
    if (threadIdx.x == 0) g_xx[p] = sh[0];
}

// ---------------- neg_dist: 64x64 register-tiled GEMM + f32x2 ------------------
__global__ void __launch_bounds__(256) negdist_kernel(const float* __restrict__ h, int C) {
    __shared__ float As[16][68];
    __shared__ float Bs[16][68];
    int b  = blockIdx.z;
    int n0 = blockIdx.y * 64, m0 = blockIdx.x * 64;
    int tid = threadIdx.x;
    int tx = tid & 15, ty = tid >> 4;
    unsigned long long acc[4][2];
    #pragma unroll
    for (int i = 0; i < 4; i++) { acc[i][0] = 0ull; acc[i][1] = 0ull; }

    for (int c0 = 0; c0 < C; c0 += 16) {
        #pragma unroll
        for (int r = 0; r < 4; r++) {
            int idx = tid + r*256;
            int cc = idx & 15, n = idx >> 4;
            int c = c0 + cc;
            As[cc][n] = (c < C) ? h[((size_t)(b*NN) + n0 + n)*C + c] : 0.f;
            Bs[cc][n] = (c < C) ? h[((size_t)(b*NN) + m0 + n)*C + c] : 0.f;
        }
        __syncthreads();
        #pragma unroll
        for (int kk = 0; kk < 16; kk++) {
            float4 a = *(const float4*)&As[kk][ty*4];
            ulonglong2 bb = *(const ulonglong2*)&Bs[kk][tx*4];
            unsigned long long a0 = pack2(a.x, a.x);
            unsigned long long a1 = pack2(a.y, a.y);
            unsigned long long a2 = pack2(a.z, a.z);
            unsigned long long a3 = pack2(a.w, a.w);
            fma2(acc[0][0], a0, bb.x); fma2(acc[0][1], a0, bb.y);
            fma2(acc[1][0], a1, bb.x); fma2(acc[1][1], a1, bb.y);
            fma2(acc[2][0], a2, bb.x); fma2(acc[2][1], a2, bb.y);
            fma2(acc[3][0], a3, bb.x); fma2(acc[3][1], a3, bb.y);
        }
        __syncthreads();
    }
    #pragma unroll
    for (int i = 0; i < 4; i++) {
        int n = n0 + ty*4 + i;
        float xn = g_xx[b*NN + n];
        #pragma unroll
        for (int jp = 0; jp < 2; jp++) {
            float lo, hi;
            unpack2(lo, hi, acc[i][jp]);
            int m = m0 + tx*4 + jp*2;
            g_dist[((size_t)(b*NN) + n)*NN + m]     = 2.f*lo - xn - g_xx[b*NN + m];
            g_dist[((size_t)(b*NN) + n)*NN + m + 1] = 2.f*hi - xn - g_xx[b*NN + m + 1];
        }
    }
}

// ------- top-k: warp/point, monotone-uint keys + redux.sync argmax -------------
// Order: value desc, index asc on ties -- identical to prior verified selection.
__global__ void topk_kernel() {
    int lane = threadIdx.x & 31;
    int p = blockIdx.x * 8 + (threadIdx.x >> 5);
    const float* row = g_dist + (size_t)p*NN;
    uint32_t u[32];
    #pragma unroll
    for (int j = 0; j < 32; j++) {
        uint32_t b = __float_as_uint(row[j*32 + lane]);
        u[j] = (b & 0x80000000u) ? ~b : (b | 0x80000000u);   // monotone, exact
    }
    // per-lane top-2 (strict >: earliest slot kept on ties)
    uint32_t m1 = 0u, m2 = 0u; int i1 = 0, i2 = 0;
    #pragma unroll
    for (int j = 0; j < 32; j++) {
        uint32_t x = u[j];
        if (x > m1) { m2 = m1; i2 = i1; m1 = x; i1 = j; }
        else if (x > m2) { m2 = x; i2 = j; }
    }
    bool have2 = true;

    for (int k = 0; k < KK; k++) {
        uint32_t um = __reduce_max_sync(0xffffffffu, m1);
        int gi = (m1 == um) ? (i1*32 + lane) : 0x7FFFFFFF;
        int gmin = __reduce_min_sync(0xffffffffu, gi);
        if (lane == 0) g_idx[p*KK + k] = gmin;
        if (gi == gmin) {                       // unique owner
            u[i1] = 0u;
            if (have2) { m1 = m2; i1 = i2; have2 = false; }
            else {
                uint32_t a = 0u, b2 = 0u; int ai = 0, bi = 0;
                #pragma unroll
                for (int j = 0; j < 32; j++) {
                    uint32_t x = u[j];
                    if (x > a) { b2 = a; bi = ai; a = x; ai = j; }
                    else if (x > b2) { b2 = x; bi = j; }
                }
                m1 = a; i1 = ai; m2 = b2; i2 = bi; have2 = true;
            }
        }
    }
}

// ------- weight transform: W(out,2C) -> fp32 packed W1 pairs + Wd -------------
__global__ void wtrans_kernel(const float* __restrict__ W, int C, int Cp, int OUT) {
    int i = blockIdx.x*256 + threadIdx.x;
    int total = (Cp >> 2) * OUT;
    if (i >= total) return;
    int o = i % OUT;
    int c4 = i / OUT;
    float w1[4], wd[4];
    #pragma unroll
    for (int j = 0; j < 4; j++) {
        int c = c4*4 + j;
        if (c < C) {
            float a = W[(size_t)o*2*C + c];
            float b2 = W[(size_t)o*2*C + C + c];
            w1[j] = a; wd[j] = b2 - a;
        } else { w1[j] = 0.f; wd[j] = 0.f; }
    }
    ulonglong2 wp;
    wp.x = pack2(w1[0], w1[1]);
    wp.y = pack2(w1[2], w1[3]);
    g_w1p[i] = wp;
    g_wdp[i] = make_float4(wd[0], wd[1], wd[2], wd[3]);
}

// ------- W1 2-way split (L3): W(out,2C) -> g_wp2 [o][c2] (hi,lo) --------------
__global__ void wsplit_kernel(const float* __restrict__ W, int C, int C2, int OUT) {
    int i = blockIdx.x*256 + threadIdx.x;
    if (i >= OUT*C2) return;
    int o = i / C2, c2 = i - o*C2;
    float w0 = W[(size_t)o*2*C + 2*c2];
    float w1 = (2*c2 + 1 < C) ? W[(size_t)o*2*C + 2*c2 + 1] : 0.f;
    __nv_bfloat16 h0 = __float2bfloat16(w0);
    __nv_bfloat16 h1 = __float2bfloat16(w1);
    uint2 v;
    v.x = ((uint32_t)*(uint16_t*)&h1 << 16) | (uint32_t)*(uint16_t*)&h0;
    v.y = packbf2(w0 - __bfloat162float(h0), w1 - __bfloat162float(h1));
    g_wp2[i] = v;
}

// ------- base = (W2-W1)*ctr per (p,o)  (L3 only) -------------------------------
__global__ void base_kernel(const float* __restrict__ h, int C, int Cp, int OUT) {
    extern __shared__ float ctr[];
    int p = blockIdx.x, o = threadIdx.x;
    for (int c = o; c < Cp; c += OUT)
        ctr[c] = (c < C) ? h[(size_t)p*C + c] : 0.f;
    __syncthreads();
    int C4 = Cp >> 2;
    const float4* c4p = (const float4*)ctr;
    float s = 0.f;
    for (int c4 = 0; c4 < C4; c4++) {
        float4 w = g_wdp[c4*OUT + o];
        float4 cv = c4p[c4];
        s += w.x*cv.x + w.y*cv.y + w.z*cv.z + w.w*cv.w;
    }
    g_base[(size_t)p*OUT + o] = s;
}

// ------- edge conv (layers 0-2): exact fp32, grouped multi-point blocks -------
// G points per block; half = OUT/2 threads per point. Arithmetic order identical
// to the verified single-point kernel (bit-identical h -> no KNN flips).
__global__ void edgeconv_kernel(const float* __restrict__ h, int C, int Cp,
                                int lc, int OUT, int foff, int G, int half) {
    extern __shared__ float sm[];
    __shared__ int nb[8*KK];
    int tid = threadIdx.x;
    int gidx = tid / half;
    int t = tid - gidx*half;
    int p = blockIdx.x * G + gidx;
    int b = p >> 10;
    float* ctr  = sm + gidx * (Cp + KK*Cp);
    float* feat = ctr + Cp;

    for (int t2 = tid; t2 < G*KK; t2 += blockDim.x)
        nb[t2] = g_idx[(blockIdx.x*G + t2/KK)*KK + (t2 - (t2/KK)*KK)];
    for (int c = t; c < Cp; c += half)
        ctr[c] = (c < C) ? h[(size_t)p*C + c] : 0.f;
    __syncthreads();
    int mask = Cp - 1;
    for (int tt = t; tt < KK*Cp; tt += half) {
        int k = tt >> lc, c = tt & mask;
        feat[tt] = (c < C) ? h[((size_t)((b << 10) + nb[gidx*KK + k]))*C + c] : 0.f;
    }
    __syncthreads();

    int o0 = t, o1 = t + half;
    int C4 = Cp >> 2;
    const float4* c4p = (const float4*)ctr;
    float base0 = 0.f, base1 = 0.f;
    for (int c4 = 0; c4 < C4; c4++) {
        float4 cv = c4p[c4];
        float4 w0 = g_wdp[c4*OUT + o0];
        float4 w1 = g_wdp[c4*OUT + o1];
        base0 += w0.x*cv.x + w0.y*cv.y + w0.z*cv.z + w0.w*cv.w;
        base1 += w1.x*cv.x + w1.y*cv.y + w1.z*cv.z + w1.w*cv.w;
    }
    const ulonglong2* f2 = (const ulonglong2*)feat;
    float mx0=-1e30f, s0=0.f, q0=0.f;
    float mx1=-1e30f, s1=0.f, q1=0.f;
    #pragma unroll
    for (int kc = 0; kc < KK; kc += 10) {
        unsigned long long a0[10], a1[10];
        #pragma unroll
        for (int k = 0; k < 10; k++) { a0[k] = 0ull; a1[k] = 0ull; }
        for (int c4 = 0; c4 < C4; c4++) {
            ulonglong2 w0 = g_w1p[c4*OUT + o0];
            ulonglong2 w1 = g_w1p[c4*OUT + o1];
            #pragma unroll
            for (int k = 0; k < 10; k++) {
                ulonglong2 fv = f2[(kc+k)*C4 + c4];
                fma2(a0[k], w0.x, fv.x); fma2(a0[k], w0.y, fv.y);
                fma2(a1[k], w1.x, fv.x); fma2(a1[k], w1.y, fv.y);
            }
        }
        #pragma unroll
        for (int k = 0; k < 10; k++) {
            float lo, hi;
            unpack2(lo, hi, a0[k]);
            float y = base0 + lo + hi;
            mx0 = fmaxf(mx0, y); s0 += y; q0 += y*y;
            unpack2(lo, hi, a1[k]);
            y = base1 + lo + hi;
            mx1 = fmaxf(mx1, y); s1 += y; q1 += y*y;
        }
    }
    g_fused[(size_t)p*512 + foff + o0] = mx0;
    g_fused[(size_t)p*512 + foff + o1] = mx1;
    g_psum[(size_t)o0*NP + p] = s0; g_pssq[(size_t)o0*NP + p] = q0;
    g_psum[(size_t)o1*NP + p] = s1; g_pssq[(size_t)o1*NP + p] = q1;
}

// ------- edge conv L3 via HMMA 2-way bf16 split (3 products) ------------------
// Block: 4 points (128 A rows = 4 x 32 padded k), 128 output cols; grid (NP/4, 2)
__global__ void __launch_bounds__(256) edgemma_kernel(
    int C2, int OUT, int foff, int nchunks)
{
    __shared__ uint32_t sA[2][128*18];
    __shared__ uint32_t sB[2][128*18];
    __shared__ int nb[80];

    int tid = threadIdx.x, wid = tid >> 5, lane = tid & 31;
    int g = lane >> 2, t = lane & 3;
    int wm = wid >> 2, wn = wid & 3;
    int pbase = blockIdx.x * 4;
    int obase = blockIdx.y * 128;
    int batch_off = (pbase >> 10) << 10;

    if (tid < 80) nb[tid] = g_idx[(pbase + tid/20)*KK + (tid - (tid/20)*20)];

    float acc[4][4][4];
    #pragma unroll
    for (int mi = 0; mi < 4; mi++)
        #pragma unroll
        for (int ni = 0; ni < 4; ni++)
            #pragma unroll
            for (int j = 0; j < 4; j++) acc[mi][ni][j] = 0.f;

    __syncthreads();

    for (int chunk = 0; chunk < nchunks; chunk++) {
        if (chunk > 0) __syncthreads();
        // A fill: 128 rows x 16 k-pairs (gathered neighbor features, uint2)
        for (int i = tid; i < 2048; i += 256) {
            int row = i >> 4, kp = i & 15;
            int k = row & 31, lp = row >> 5;
            int c2 = chunk*16 + kp;
            uint2 v = make_uint2(0u, 0u);
            if (k < KK && c2 < C2)
                v = g_hp[(size_t)(batch_off + nb[lp*20 + k])*C2 + c2];
            sA[0][row*18 + kp] = v.x;
            sA[1][row*18 + kp] = v.y;
        }
        // B fill: 128 weight rows x 16 k-pairs (uint2)
        for (int i = tid; i < 2048; i += 256) {
            int row = i >> 4, kp = i & 15;
            int c2 = chunk*16 + kp;
            uint2 v = make_uint2(0u, 0u);
            if (c2 < C2)
                v = g_wp2[(size_t)(obase + row)*C2 + c2];
            sB[0][row*18 + kp] = v.x;
            sB[1][row*18 + kp] = v.y;
        }
        __syncthreads();
        #pragma unroll
        for (int ks = 0; ks < 2; ks++) {
            int kp0 = ks * 8;
            uint32_t af[2][4][4];
            #pragma unroll
            for (int a = 0; a < 2; a++)
                #pragma unroll
                for (int mi = 0; mi < 4; mi++) {
                    int r = wm*64 + mi*16 + g;
                    af[a][mi][0] = sA[a][r*18 + kp0 + t];
                    af[a][mi][1] = sA[a][(r+8)*18 + kp0 + t];
                    af[a][mi][2] = sA[a][r*18 + kp0 + 4 + t];
                    af[a][mi][3] = sA[a][(r+8)*18 + kp0 + 4 + t];
                }
            uint32_t bf[2][4][2];
            #pragma unroll
            for (int a = 0; a < 2; a++)
                #pragma unroll
                for (int ni = 0; ni < 4; ni++) {
                    int n = wn*32 + ni*8 + g;
                    bf[a][ni][0] = sB[a][n*18 + kp0 + t];
                    bf[a][ni][1] = sB[a][n*18 + kp0 + 4 + t];
                }
            #pragma unroll
            for (int mi = 0; mi < 4; mi++)
                #pragma unroll
                for (int ni = 0; ni < 4; ni++) {
                    mma16816(acc[mi][ni], af[0][mi], bf[0][ni]);
                    mma16816(acc[mi][ni], af[0][mi], bf[1][ni]);
                    mma16816(acc[mi][ni], af[1][mi], bf[0][ni]);
                }
        }
    }

    // epilogue: per-point max / sum / sumsq over valid k rows
    #pragma unroll
    for (int half = 0; half < 2; half++) {
        int p = pbase + wm*2 + half;
        #pragma unroll
        for (int ni = 0; ni < 4; ni++) {
            #pragma unroll
            for (int j = 0; j < 2; j++) {
                float v0 = acc[half*2][ni][j];       // k = g
                float v1 = acc[half*2][ni][j+2];     // k = g+8
                float v2 = acc[half*2+1][ni][j];     // k = 16+g (valid g<4)
                bool ok2 = (g < 4);
                float mx = fmaxf(v0, v1);
                if (ok2) mx = fmaxf(mx, v2);
                float s = v0 + v1 + (ok2 ? v2 : 0.f);
                float q = v0*v0 + v1*v1 + (ok2 ? v2*v2 : 0.f);
                #pragma unroll
                for (int off = 4; off <= 16; off <<= 1) {
                    mx = fmaxf(mx, __shfl_xor_sync(0xffffffffu, mx, off));
                    s += __shfl_xor_sync(0xffffffffu, s, off);
                    q += __shfl_xor_sync(0xffffffffu, q, off);
                }
                if (g == 0) {
                    int o = obase + wn*32 + ni*8 + t*2 + j;
                    float b = g_base[(size_t)p*OUT + o];
                    g_fused[(size_t)p*512 + foff + o] = mx + b;
                    g_psum[(size_t)o*NP + p] = s + 20.f*b;
                    g_pssq[(size_t)o*NP + p] = q + 2.f*b*s + 20.f*b*b;
                }
            }
        }
    }
}

// ---------------- per-channel BN stats (coalesced, deterministic) -------------
__global__ void chanstats_kernel(const float* __restrict__ g,
                                 const float* __restrict__ bta,
                                 int P, float invM) {
    int o = blockIdx.x;
    __shared__ float ssum[256], ssq[256];
    const float* ps = g_psum + (size_t)o*P;
    const float* pq = g_pssq + (size_t)o*P;
    float s = 0.f, q = 0.f;
    for (int i = threadIdx.x; i < P; i += 256) { s += ps[i]; q += pq[i]; }
    ssum[threadIdx.x] = s; ssq[threadIdx.x] = q;
    __syncthreads();
    for (int st = 128; st > 0; st >>= 1) {
        if (threadIdx.x < st) {
            ssum[threadIdx.x] += ssum[threadIdx.x + st];
            ssq [threadIdx.x] += ssq [threadIdx.x + st];
        }
        __syncthreads();
    }
    if (threadIdx.x == 0) {
        float mean = ssum[0] * invM;
        float var  = ssq[0] * invM - mean*mean;
        float sc   = rsqrtf(var + 1e-5f) * g[o];
        g_scale[o] = sc;
        g_shift[o] = bta[o] - mean * sc;
    }
}

// -- BN + LeakyReLU; optional fp32 hnext + ||h||^2; optional 2-way bf16 split --
__global__ void normedge_kernel(int OUT, int foff, float* __restrict__ hnext,
                                int wantnext, int wantsplit) {
    __shared__ float sh[256];
    int p = blockIdx.x, o = threadIdx.x;
    float v = g_fused[(size_t)p*512 + foff + o] * g_scale[o] + g_shift[o];
    v = v > 0.f ? v : 0.2f*v;
    g_fused[(size_t)p*512 + foff + o] = v;
    float vo = __shfl_xor_sync(0xffffffffu, v, 1);
    if (wantnext) hnext[(size_t)p*OUT + o] = v;
    if (wantsplit && !(o & 1)) {
        __nv_bfloat16 h0 = __float2bfloat16(v);
        __nv_bfloat16 h1 = __float2bfloat16(vo);
        uint2 hv;
        hv.x = ((uint32_t)*(uint16_t*)&h1 << 16) | (uint32_t)*(uint16_t*)&h0;
        hv.y = packbf2(v - __bfloat162float(h0), vo - __bfloat162float(h1));
        g_hp[(size_t)p*(OUT/2) + (o >> 1)] = hv;
    }
    sh[o] = v*v;
    __syncthreads();
    for (int st = OUT >> 1; st > 0; st >>= 1) {
        if (o < st) sh[o] += sh[o + st];
        __syncthreads();
    }
    if (o == 0 && wantnext) g_xx[p] = sh[0];
}

// ---------------- split Wf into bf16 hi/lo -------------------------------------
__global__ void wfsplit_kernel(const float* __restrict__ Wf) {
    int i = blockIdx.x*256 + threadIdx.x;
    if (i >= 1024*512) return;
    float w = Wf[i];
    __nv_bfloat16 h = __float2bfloat16(w);
    float r = w - __bfloat162float(h);
    g_bh[i] = h;
    g_bl[i] = __float2bfloat16(r);
}

// ---------------- final linear via HMMA bf16-split ----------------------------
__global__ void __launch_bounds__(256) finalmma_kernel(float* __restrict__ out) {
    __shared__ uint32_t sAh[128*18], sAl[128*18];
    __shared__ uint32_t sBh[128*18], sBl[128*18];
    __shared__ float red[2][2][128];

    int tid = threadIdx.x, wid = tid >> 5, lane = tid & 31;
    int g = lane >> 2, t = lane & 3;
    int wm = wid >> 2, wn = wid & 3;
    int pb = blockIdx.x, ob = blockIdx.y;
    int pbase = pb * 128, obase = ob * 128;

    float acc[4][4][4];
    #pragma unroll
    for (int mi = 0; mi < 4; mi++)
        #pragma unroll
        for (int ni = 0; ni < 4; ni++)
            #pragma unroll
            for (int j = 0; j < 4; j++) acc[mi][ni][j] = 0.f;

    const uint32_t* bh2 = (const uint32_t*)g_bh;
    const uint32_t* bl2 = (const uint32_t*)g_bl;

    for (int c0 = 0; c0 < 512; c0 += 32) {
        __syncthreads();
        #pragma unroll
        for (int i = tid; i < 2048; i += 256) {
            int row = i >> 4, kp = i & 15;
            float2 v = *(const float2*)&g_fused[(size_t)(pbase + row)*512 + c0 + kp*2];
            __nv_bfloat16 h0 = __float2bfloat16(v.x);
            __nv_bfloat16 h1 = __float2bfloat16(v.y);
            float r0 = v.x - __bfloat162float(h0);
            float r1 = v.y - __bfloat162float(h1);
            __nv_bfloat162 hp; hp.x = h0; hp.y = h1;
            sAh[row*18 + kp] = *(uint32_t*)&hp;
            sAl[row*18 + kp] = packbf2(r0, r1);
            size_t gi = (size_t)(obase + row)*256 + (c0 >> 1) + kp;
            sBh[row*18 + kp] = bh2[gi];
            sBl[row*18 + kp] = bl2[gi];
        }
        __syncthreads();
        #pragma unroll
        for (int ks = 0; ks < 2; ks++) {
            int kp0 = ks * 8;
            uint32_t ah[4][4], al[4][4];
            #pragma unroll
            for (int mi = 0; mi < 4; mi++) {
                int r = wm*64 + mi*16 + g;
                ah[mi][0] = sAh[r*18 + kp0 + t];
                ah[mi][1] = sAh[(r+8)*18 + kp0 + t];
                ah[mi][2] = sAh[r*18 + kp0 + 4 + t];
                ah[mi][3] = sAh[(r+8)*18 + kp0 + 4 + t];
                al[mi][0] = sAl[r*18 + kp0 + t];
                al[mi][1] = sAl[(r+8)*18 + kp0 + t];
                al[mi][2] = sAl[r*18 + kp0 + 4 + t];
                al[mi][3] = sAl[(r+8)*18 + kp0 + 4 + t];
            }
            uint32_t bh[4][2], bl[4][2];
            #pragma unroll
            for (int ni = 0; ni < 4; ni++) {
                int n = wn*32 + ni*8 + g;
                bh[ni][0] = sBh[n*18 + kp0 + t];
                bh[ni][1] = sBh[n*18 + kp0 + 4 + t];
                bl[ni][0] = sBl[n*18 + kp0 + t];
                bl[ni][1] = sBl[n*18 + kp0 + 4 + t];
            }
            #pragma unroll
            for (int mi = 0; mi < 4; mi++)
                #pragma unroll
                for (int ni = 0; ni < 4; ni++) {
                    mma16816(acc[mi][ni], ah[mi], bh[ni]);
                    mma16816(acc[mi][ni], ah[mi], bl[ni]);
                    mma16816(acc[mi][ni], al[mi], bh[ni]);
                }
        }
    }

    #pragma unroll
    for (int ni = 0; ni < 4; ni++) {
        float s0 = 0.f, s1 = 0.f, q0 = 0.f, q1 = 0.f;
        #pragma unroll
        for (int mi = 0; mi < 4; mi++) {
            float* a = acc[mi][ni];
            int row = pbase + wm*64 + mi*16 + g;
            int col = obase + wn*32 + ni*8 + t*2;
            *(float2*)&out[(size_t)row*1024 + col]     = make_float2(a[0], a[1]);
            *(float2*)&out[(size_t)(row+8)*1024 + col] = make_float2(a[2], a[3]);
            s0 += a[0] + a[2]; s1 += a[1] + a[3];
            q0 += a[0]*a[0] + a[2]*a[2];
            q1 += a[1]*a[1] + a[3]*a[3];
        }
        #pragma unroll
        for (int off = 4; off < 32; off <<= 1) {
            s0 += __shfl_xor_sync(0xffffffffu, s0, off);
            s1 += __shfl_xor_sync(0xffffffffu, s1, off);
            q0 += __shfl_xor_sync(0xffffffffu, q0, off);
            q1 += __shfl_xor_sync(0xffffffffu, q1, off);
        }
        if (g == 0) {
            int colw = wn*32 + ni*8 + t*2;
            red[wm][0][colw]   = s0;
            red[wm][0][colw+1] = s1;
            red[wm][1][colw]   = q0;
            red[wm][1][colw+1] = q1;
        }
    }
    __syncthreads();
    if (tid < 128) {
        float s = red[0][0][tid] + red[1][0][tid];
        float q = red[0][1][tid] + red[1][1][tid];
        g_psum[(size_t)(obase + tid)*64 + pb] = s;
        g_pssq[(size_t)(obase + tid)*64 + pb] = q;
    }
}

// ---------------- final BN + LeakyReLU in place (float4) -----------------------
__global__ void normout_kernel(float* __restrict__ out) {
    int i = blockIdx.x*256 + threadIdx.x;
    if (i >= NP*256) return;
    int ob = (i & 255) * 4;
    float4 v = ((float4*)out)[i];
    v.x = v.x * g_scale[ob+0] + g_shift[ob+0];
    v.y = v.y * g_scale[ob+1] + g_shift[ob+1];
    v.z = v.z * g_scale[ob+2] + g_shift[ob+2];
    v.w = v.w * g_scale[ob+3] + g_shift[ob+3];
    v.x = v.x > 0.f ? v.x : 0.2f*v.x;
    v.y = v.y > 0.f ? v.y : 0.2f*v.y;
    v.z = v.z > 0.f ? v.z : 0.2f*v.z;
    v.w = v.w > 0.f ? v.w : 0.2f*v.w;
    ((float4*)out)[i] = v;
}

// ------------------------------- launcher -------------------------------------
extern "C" void kernel_launch(void* const* d_in, const int* in_sizes, int n_in,
                              void* d_out, int out_size) {
    (void)in_sizes; (void)n_in; (void)out_size;
    const float* x  = (const float*)d_in[0];
    const float* W[4]  = {(const float*)d_in[1],  (const float*)d_in[4],
                          (const float*)d_in[7],  (const float*)d_in[10]};
    const float* ga[4] = {(const float*)d_in[2],  (const float*)d_in[5],
                          (const float*)d_in[8],  (const float*)d_in[11]};
    const float* bt[4] = {(const float*)d_in[3],  (const float*)d_in[6],
                          (const float*)d_in[9],  (const float*)d_in[12]};
    const float* Wf = (const float*)d_in[13];
    const float* gf = (const float*)d_in[14];
    const float* bf = (const float*)d_in[15];
    float* out = (float*)d_out;

    float *h1, *h2;
    cudaGetSymbolAddress((void**)&h1, g_h1);
    cudaGetSymbolAddress((void**)&h2, g_h2);
    float* hn[2] = {h1, h2};

    const int Cs[4]     = {3, 64, 64, 128};
    const int Cps[4]    = {4, 64, 64, 128};
    const int lcs[4]    = {2, 6, 6, 7};
    const int OUTs[4]   = {64, 64, 128, 256};
    const int foffs[4]  = {0, 64, 128, 256};
    const int Gs[4]     = {8, 4, 2, 0};

    wfsplit_kernel<<<(1024*512 + 255)/256, 256>>>(Wf);
    xx_kernel<<<NP, 64>>>(x, 3);

    const float* hcur = x;
    for (int i = 0; i < 4; i++) {
        int C = Cs[i], Cp = Cps[i], OUT = OUTs[i];
        negdist_kernel<<<dim3(NN/64, NN/64, BB), 256>>>(hcur, C);
        topk_kernel<<<NP/8, 256>>>();
        int wtot = (Cp/4)*OUT;
        wtrans_kernel<<<(wtot + 255)/256, 256>>>(W[i], C, Cp, OUT);
        if (i < 3) {
            int G = Gs[i], half = OUT/2;
            size_t smem = (size_t)G * (Cp + KK*Cp) * sizeof(float);
            edgeconv_kernel<<<NP/G, G*half, smem>>>(hcur, C, Cp, lcs[i], OUT,
                                                    foffs[i], G, half);
        } else {
            int C2 = C/2;
            wsplit_kernel<<<(OUT*C2 + 255)/256, 256>>>(W[i], C, C2, OUT);
            base_kernel<<<NP, OUT, Cp*sizeof(float)>>>(hcur, C, Cp, OUT);
            edgemma_kernel<<<dim3(NP/4, 2), 256>>>(C2, OUT, foffs[i], C2/16);
        }
        chanstats_kernel<<<OUT, 256>>>(ga[i], bt[i], NP, 1.f/((float)NP*KK));
        int wantnext = (i < 3) ? 1 : 0;
        int wantsplit = (i == 2) ? 1 : 0;
        normedge_kernel<<<NP, OUT>>>(OUT, foffs[i], hn[i & 1], wantnext, wantsplit);
        hcur = hn[i & 1];
    }

    finalmma_kernel<<<dim3(64, 8), 256>>>(out);
    chanstats_kernel<<<1024, 256>>>(gf, bf, 64, 1.f/(float)NP);
    normout_kernel<<<(NP*256 + 255)/256, 256>>>(out);
}